// round 14
// baseline (speedup 1.0000x reference)
#include <cuda_runtime.h>
#include <cuda_bf16.h>
#include <math.h>
#include <stdint.h>

#define NATOM 50000
#define MNBR  12
#define AF    64
#define NBRF  41
#define ORIG  92
#define NCONV 3
#define NM    (NATOM*MNBR)
#define BCRY  500
#define NACRY 100
#define BN_EPS 1e-5f

// ---------------- scratch ----------------
static __device__ float g_h[NATOM*AF];
static __device__ __nv_bfloat16 g_hbf[NATOM*AF];
static __device__ __nv_bfloat16 g_CHb[NATOM*256];
static __device__ __nv_bfloat16 g_gatedb[(size_t)NM*128];
static __device__ __nv_bfloat16 g_nbrb[(size_t)(NM+128)*48];  // bf16 nbr_fea, K padded to 48, slack rows
static __device__ float g_summed[NATOM*AF];
static __device__ uint32_t g_BfC[NCONV*3072];
static __device__ uint32_t g_BfP[NCONV*8192];
static __device__ float g_stats1[NCONV*256];
static __device__ float g_stats2[NCONV*128];
static __device__ float g_inv[NATOM];
static __device__ float g_pooled[BCRY*AF];

__device__ __forceinline__ float softplus_f(float x) {
    return fmaxf(x, 0.f) + log1pf(expf(-fabsf(x)));
}
__device__ __forceinline__ float sigmoid_f(float x) {
    return 1.f / (1.f + expf(-x));
}
__device__ __forceinline__ float softplus_fast(float x) {
    return fmaxf(x, 0.f) + __logf(1.f + __expf(-fabsf(x)));
}
__device__ __forceinline__ float sigmoid_fast(float x) {
    return 1.f / (1.f + __expf(-x));
}
__device__ __forceinline__ uint32_t packbf(float a, float b) {
    __nv_bfloat162 t = __floats2bfloat162_rn(a, b);
    return *reinterpret_cast<uint32_t*>(&t);
}
__device__ __forceinline__ void mma16816(float d[4], const uint32_t a[4], uint32_t b0, uint32_t b1) {
    asm volatile(
        "mma.sync.aligned.m16n8k16.row.col.f32.bf16.bf16.f32 "
        "{%0,%1,%2,%3},{%4,%5,%6,%7},{%8,%9},{%0,%1,%2,%3};\n"
        : "+f"(d[0]), "+f"(d[1]), "+f"(d[2]), "+f"(d[3])
        : "r"(a[0]), "r"(a[1]), "r"(a[2]), "r"(a[3]), "r"(b0), "r"(b1));
}

// ---------------- one-time: nbr_fea -> bf16, K padded 41->48, slack rows zeroed ----------------
__global__ void k_cvt_nbr(const float* __restrict__ nbr_fea) {
    size_t idx = (size_t)blockIdx.x * 256 + threadIdx.x;   // over (NM+128)*48
    if (idx >= (size_t)(NM+128)*48) return;
    int k = (int)(idx % 48);
    size_t e = idx / 48;
    float v = (e < (size_t)NM && k < 41) ? nbr_fea[e*41 + k] : 0.f;
    g_nbrb[idx] = __float2bfloat16(v);
}

// ---------------- weights -> mma B-fragments + zero stats ----------------
__global__ void k_prepw_all(const float* __restrict__ Wbase) {
    int gidx = blockIdx.x * 256 + threadIdx.x;
    if (gidx < NCONV*256) g_stats1[gidx] = 0.f;
    if (gidx < NCONV*128) g_stats2[gidx] = 0.f;
    int per = 3072 + 8192;
    if (gidx >= NCONV*per) return;
    int l = gidx / per;
    int idx = gidx % per;
    const float* W = Wbase + (size_t)l*128*169;
    if (idx < 3072) {
        int r = idx & 1, ln = (idx >> 1) & 31, t = (idx >> 6) & 15, s = idx >> 10;
        int gid = ln >> 2, tig = ln & 3;
        int n = t*8 + gid;
        int k0 = s*16 + tig*2 + (r ? 8 : 0);
        float w0 = (k0   < 41) ? W[n*169 + 128 + k0]   : 0.f;
        float w1 = (k0+1 < 41) ? W[n*169 + 128 + k0+1] : 0.f;
        g_BfC[l*3072 + idx] = packbf(w0, w1);
    } else {
        int i2 = idx - 3072;
        int r = i2 & 1, ln = (i2 >> 1) & 31, t = (i2 >> 6) & 15, s = (i2 >> 10) & 3, cy = i2 >> 12;
        int gid = ln >> 2, tig = ln & 3;
        int n = cy*128 + t*8 + gid;
        int k0 = s*16 + tig*2 + (r ? 8 : 0);
        float w0, w1;
        if (n < 128) { w0 = W[n*169 + k0]; w1 = W[n*169 + k0 + 1]; }
        else         { w0 = W[(n-128)*169 + 64 + k0]; w1 = W[(n-128)*169 + 64 + k0 + 1]; }
        g_BfP[l*8192 + i2] = packbf(w0, w1);
    }
}

// ---------------- embedding ----------------
__global__ void k_embed(const float* __restrict__ atom_fea,
                        const float* __restrict__ mask,
                        const float* __restrict__ embW,
                        float* __restrict__ out_masked) {
    __shared__ float s_x[64][93];
    __shared__ float s_WT[92][64];
    int r0 = blockIdx.x * 64;
    int tid = threadIdx.x;
    int nrows = NATOM - r0; if (nrows > 64) nrows = 64;

    for (int i = tid; i < 92*64; i += 256) { int o = i / 92, k = i % 92; s_WT[k][o] = embW[i]; }
    for (int i = tid; i < nrows*92; i += 256) {
        int rr = i / 92, k = i % 92;
        float v = atom_fea[(size_t)(r0+rr)*92 + k] * mask[k];
        s_x[rr][k] = v;
        out_masked[(size_t)(r0+rr)*92 + k] = v;
    }
    __syncthreads();

    int ty = tid / 16, tx = tid % 16;
    float acc[4][4] = {};
    for (int k = 0; k < 92; k++) {
        float b0 = s_WT[k][tx*4+0], b1 = s_WT[k][tx*4+1];
        float b2 = s_WT[k][tx*4+2], b3 = s_WT[k][tx*4+3];
        #pragma unroll
        for (int i = 0; i < 4; i++) {
            float a = s_x[ty*4+i][k];
            acc[i][0] += a*b0; acc[i][1] += a*b1; acc[i][2] += a*b2; acc[i][3] += a*b3;
        }
    }
    #pragma unroll
    for (int i = 0; i < 4; i++) {
        int r = r0 + ty*4 + i;
        if (r < NATOM) {
            #pragma unroll
            for (int j = 0; j < 4; j++) {
                g_h[r*64 + tx*4 + j] = acc[i][j];
                g_hbf[r*64 + tx*4 + j] = __float2bfloat16(acc[i][j]);
            }
        }
    }
}

// ---------------- CH = h @ [Wc^T | Wn^T], 512 threads (R12-proven) ----------------
__global__ __launch_bounds__(512, 2) void k_pre_mma(const uint32_t* __restrict__ BfP) {
    __shared__ __align__(16) unsigned char s_u[34816];
    __nv_bfloat16 (*s_A)[72] = (__nv_bfloat16(*)[72])s_u;
    uint32_t* s_Bf = (uint32_t*)(s_u + 18432);
    __nv_bfloat16 (*s_D)[136] = (__nv_bfloat16(*)[136])s_u;

    int r0 = blockIdx.x * 128;
    int cy = blockIdx.y;
    int tid = threadIdx.x;
    int nvalid = NATOM - r0; if (nvalid > 128) nvalid = 128;

    for (int i = tid; i < 4608; i += 512) ((uint32_t*)s_u)[i] = 0;
    __syncthreads();
    for (int i = tid; i < nvalid*32; i += 512) {
        int row = i >> 5, kk = i & 31;
        ((uint32_t*)s_u)[row*36 + kk] = ((const uint32_t*)g_hbf)[(size_t)(r0+row)*32 + kk];
    }
    for (int i = tid; i < 4096; i += 512) s_Bf[i] = BfP[cy*4096 + i];
    __syncthreads();

    int wid = tid >> 5, lane = tid & 31, gid = lane >> 2, tig = lane & 3;
    int wm = wid & 3, wn = wid >> 2;
    float acc[2][4][4];
    #pragma unroll
    for (int mt = 0; mt < 2; mt++)
        #pragma unroll
        for (int t = 0; t < 4; t++)
            #pragma unroll
            for (int j = 0; j < 4; j++) acc[mt][t][j] = 0.f;

    #pragma unroll
    for (int s = 0; s < 4; s++) {
        uint32_t a[2][4];
        #pragma unroll
        for (int mt = 0; mt < 2; mt++) {
            int row = wm*32 + mt*16 + gid;
            int kb = s*16 + 2*tig;
            a[mt][0] = *(const uint32_t*)&s_A[row][kb];
            a[mt][1] = *(const uint32_t*)&s_A[row+8][kb];
            a[mt][2] = *(const uint32_t*)&s_A[row][kb+8];
            a[mt][3] = *(const uint32_t*)&s_A[row+8][kb+8];
        }
        #pragma unroll
        for (int t = 0; t < 4; t++) {
            int gt = wn*4 + t;
            uint32_t b0 = s_Bf[((s*16+gt)*32+lane)*2];
            uint32_t b1 = s_Bf[((s*16+gt)*32+lane)*2 + 1];
            mma16816(acc[0][t], a[0], b0, b1);
            mma16816(acc[1][t], a[1], b0, b1);
        }
    }
    __syncthreads();
    #pragma unroll
    for (int mt = 0; mt < 2; mt++)
        #pragma unroll
        for (int t = 0; t < 4; t++) {
            int row = wm*32 + mt*16 + gid;
            int col = wn*32 + t*8 + 2*tig;
            *(uint32_t*)&s_D[row][col]   = packbf(acc[mt][t][0], acc[mt][t][1]);
            *(uint32_t*)&s_D[row+8][col] = packbf(acc[mt][t][2], acc[mt][t][3]);
        }
    __syncthreads();

    int ty = tid >> 4, tx = tid & 15;
    #pragma unroll
    for (int i = 0; i < 4; i++) {
        int r = ty*4 + i;
        if (r0 + r < NATOM)
            *(uint4*)&g_CHb[(size_t)(r0+r)*256 + cy*128 + tx*8] = *(const uint4*)&s_D[r][tx*8];
    }
}

// ---------------- main conv: R12 structure + bf16 A tile (no zero pass, no cvt, no div/mod) ----------------
__global__ __launch_bounds__(256, 2) void k_conv_mma(const int*   __restrict__ nbr_idx,
                                                     const float* __restrict__ bias,
                                                     const uint32_t* __restrict__ BfC,
                                                     float* __restrict__ stats1) {
    __shared__ __align__(16) unsigned char s_u[34816];
    __nv_bfloat16 (*s_A)[56] = (__nv_bfloat16(*)[56])s_u;      // 128 x 56; cols 0-47 valid
    uint32_t* s_Bf = (uint32_t*)(s_u + 14336);                  // 3072 words
    __nv_bfloat16 (*s_D)[136] = (__nv_bfloat16(*)[136])s_u;     // reuse after mma
    __shared__ __align__(16) __nv_bfloat16 s_cc[12][128];
    __shared__ int   s_n[128], s_nbr[128];
    __shared__ float s_sum[128], s_sq[128], s_bias[128];

    int r0 = blockIdx.x * 128;
    int a0 = r0 / 12;
    int tid = threadIdx.x;

    // A tile: 128 rows x 48 bf16 (pre-padded, pre-zeroed) = 768 uint4 copies
    for (int i = tid; i < 768; i += 256) {
        int r = i / 6, c = i % 6;
        *(uint4*)&s_A[r][c*8] = *(const uint4*)&g_nbrb[(size_t)(r0+r)*48 + c*8];
    }
    for (int i = tid; i < 3072; i += 256) s_Bf[i] = BfC[i];
    for (int i = tid; i < 12*16; i += 256) {
        int row = i >> 4, c = i & 15;
        int atom = a0 + row; if (atom > NATOM-1) atom = NATOM-1;
        *(uint4*)&s_cc[row][c*8] = *(const uint4*)&g_CHb[(size_t)atom*256 + c*8];
    }
    if (tid < 128) {
        int e = r0 + tid;
        s_nbr[tid] = (e < NM) ? nbr_idx[e] : 0;
        s_n[tid]   = (e < NM) ? e / 12 - a0 : 0;
        s_sum[tid] = 0.f; s_sq[tid] = 0.f; s_bias[tid] = bias[tid];
    }
    __syncthreads();

    int wid = tid >> 5, lane = tid & 31, gid = lane >> 2, tig = lane & 3;
    int wm = wid & 3, wn = wid >> 2;
    float acc[2][8][4];
    #pragma unroll
    for (int mt = 0; mt < 2; mt++)
        #pragma unroll
        for (int t = 0; t < 8; t++)
            #pragma unroll
            for (int j = 0; j < 4; j++) acc[mt][t][j] = 0.f;

    #pragma unroll
    for (int s = 0; s < 3; s++) {
        uint32_t a[2][4];
        #pragma unroll
        for (int mt = 0; mt < 2; mt++) {
            int row = wm*32 + mt*16 + gid;
            int kb = s*16 + 2*tig;
            a[mt][0] = *(const uint32_t*)&s_A[row][kb];
            a[mt][1] = *(const uint32_t*)&s_A[row+8][kb];
            a[mt][2] = *(const uint32_t*)&s_A[row][kb+8];
            a[mt][3] = *(const uint32_t*)&s_A[row+8][kb+8];
        }
        #pragma unroll
        for (int t = 0; t < 8; t++) {
            int gt = wn*8 + t;
            uint32_t b0 = s_Bf[((s*16+gt)*32+lane)*2];
            uint32_t b1 = s_Bf[((s*16+gt)*32+lane)*2 + 1];
            mma16816(acc[0][t], a[0], b0, b1);
            mma16816(acc[1][t], a[1], b0, b1);
        }
    }
    __syncthreads();
    #pragma unroll
    for (int mt = 0; mt < 2; mt++)
        #pragma unroll
        for (int t = 0; t < 8; t++) {
            int row = wm*32 + mt*16 + gid;
            int col = wn*64 + t*8 + 2*tig;
            *(uint32_t*)&s_D[row][col]   = packbf(acc[mt][t][0], acc[mt][t][1]);
            *(uint32_t*)&s_D[row+8][col] = packbf(acc[mt][t][2], acc[mt][t][3]);
        }
    __syncthreads();

    int ty = tid >> 4, tx = tid & 15;
    float bs[8], cs[8], cq[8];
    #pragma unroll
    for (int j = 0; j < 8; j++) { bs[j] = s_bias[tx*8 + j]; cs[j] = 0.f; cq[j] = 0.f; }

    uint4 cn4[8];
    #pragma unroll
    for (int i = 0; i < 8; i++) {
        int lr = ty*8 + i;
        cn4[i] = *(const uint4*)&g_CHb[(size_t)s_nbr[lr]*256 + 128 + tx*8];
    }
    #pragma unroll
    for (int i = 0; i < 8; i++) {
        int lr = ty*8 + i;
        int e = r0 + lr;
        if (e < NM) {
            uint4 cc4 = *(const uint4*)&s_cc[s_n[lr]][tx*8];
            const uint32_t* ccw = (const uint32_t*)&cc4;
            const uint32_t* cnw = (const uint32_t*)&cn4[i];
            const __nv_bfloat162* dd = (const __nv_bfloat162*)&s_D[lr][tx*8];
            uint32_t o[4];
            #pragma unroll
            for (int jj = 0; jj < 4; jj++) {
                float2 d2 = __bfloat1622float2(dd[jj]);
                float2 c2 = __bfloat1622float2(*(const __nv_bfloat162*)&ccw[jj]);
                float2 n2 = __bfloat1622float2(*(const __nv_bfloat162*)&cnw[jj]);
                float v0 = d2.x + c2.x + n2.x + bs[2*jj];
                float v1 = d2.y + c2.y + n2.y + bs[2*jj+1];
                cs[2*jj]   += v0; cq[2*jj]   += v0*v0;
                cs[2*jj+1] += v1; cq[2*jj+1] += v1*v1;
                o[jj] = packbf(v0, v1);
            }
            *(uint4*)&g_gatedb[(size_t)e*128 + tx*8] = make_uint4(o[0], o[1], o[2], o[3]);
        }
    }
    #pragma unroll
    for (int j = 0; j < 8; j++) {
        atomicAdd(&s_sum[tx*8+j], cs[j]);
        atomicAdd(&s_sq[tx*8+j],  cq[j]);
    }
    __syncthreads();
    if (tid < 128) {
        atomicAdd(&stats1[tid],       s_sum[tid]);
        atomicAdd(&stats1[128 + tid], s_sq[tid]);
    }
}

// ---------------- BN1-apply + activation + sum over M + BN2 stats ----------------
__global__ void k_act(const float* __restrict__ g1, const float* __restrict__ b1,
                      const float* __restrict__ stats1, float* __restrict__ stats2) {
    __shared__ float s_bnp[256];
    __shared__ float s_s[64], s_q[64];
    int tid = threadIdx.x;
    int lane = tid & 31;
    int an = blockIdx.x*8 + (tid >> 5);
    if (tid < 64) { s_s[tid] = 0.f; s_q[tid] = 0.f; }
    if (tid < 128) {
        float s = stats1[tid], q = stats1[128+tid];
        float inv = 1.f / (float)NM;
        float mu = s * inv;
        float var = q * inv - mu*mu;
        float a = g1[tid] * rsqrtf(var + BN_EPS);
        s_bnp[tid] = a;
        s_bnp[128+tid] = b1[tid] - mu*a;
    }
    __syncthreads();

    float2 af = *(const float2*)&s_bnp[2*lane];
    float2 ac = *(const float2*)&s_bnp[64 + 2*lane];
    float2 cf = *(const float2*)&s_bnp[128 + 2*lane];
    float2 cc = *(const float2*)&s_bnp[192 + 2*lane];
    const __nv_bfloat162* gp = (const __nv_bfloat162*)&g_gatedb[(size_t)an*1536];
    float sx = 0.f, sy = 0.f;
    #pragma unroll
    for (int m = 0; m < 12; m++) {
        float2 f = __bfloat1622float2(gp[m*64 + lane]);
        float2 c = __bfloat1622float2(gp[m*64 + 32 + lane]);
        sx += sigmoid_fast(af.x*f.x + cf.x) * softplus_fast(ac.x*c.x + cc.x);
        sy += sigmoid_fast(af.y*f.y + cf.y) * softplus_fast(ac.y*c.y + cc.y);
    }
    *(float2*)&g_summed[(size_t)an*64 + 2*lane] = make_float2(sx, sy);
    atomicAdd(&s_s[2*lane],   sx);
    atomicAdd(&s_s[2*lane+1], sy);
    atomicAdd(&s_q[2*lane],   sx*sx);
    atomicAdd(&s_q[2*lane+1], sy*sy);
    __syncthreads();
    if (tid < 64) {
        atomicAdd(&stats2[tid],      s_s[tid]);
        atomicAdd(&stats2[64 + tid], s_q[tid]);
    }
}

// ---------------- residual + softplus (+ optional fused norm) ----------------
__global__ void k_update(const float* __restrict__ g2, const float* __restrict__ b2,
                         const float* __restrict__ stats2, int do_norm) {
    __shared__ float s_bnp[128];
    __shared__ float s_nrm[4];
    int tid = threadIdx.x;
    if (tid < 64) {
        float s = stats2[tid], q = stats2[64+tid];
        float inv = 1.f / (float)NATOM;
        float mu = s * inv;
        float var = q * inv - mu*mu;
        float a = g2[tid] * rsqrtf(var + BN_EPS);
        s_bnp[tid] = a;
        s_bnp[64+tid] = b2[tid] - mu*a;
    }
    if (tid < 4) s_nrm[tid] = 0.f;
    __syncthreads();
    int idx = blockIdx.x*256 + tid;
    int j = idx & 63;
    float v = g_h[idx] + s_bnp[j]*g_summed[idx] + s_bnp[64+j];
    float r = softplus_f(v);
    g_h[idx] = r;
    g_hbf[idx] = __float2bfloat16(r);
    if (do_norm) {
        float ss = r*r;
        #pragma unroll
        for (int off = 16; off; off >>= 1) ss += __shfl_xor_sync(0xffffffffu, ss, off);
        int la = tid >> 6;
        if ((tid & 31) == 0) atomicAdd(&s_nrm[la], ss);
        __syncthreads();
        if ((tid & 63) == 0) {
            int n = idx >> 6;
            g_inv[n] = 1.f / fmaxf(sqrtf(s_nrm[la]), 1e-12f);
        }
    }
}

// ---------------- crystal pooling ----------------
__global__ void k_pool(const int* __restrict__ cai) {
    int b = blockIdx.x, j = threadIdx.x;
    float s = 0.f;
    for (int a = 0; a < NACRY; a++) {
        int idx = cai[b*NACRY + a];
        s += g_h[(size_t)idx*64 + j] * g_inv[idx];
    }
    g_pooled[b*64 + j] = s * (1.f / (float)NACRY);
}

// ---------------- final MLP ----------------
__global__ void k_mlp(const float* __restrict__ fc1_W, const float* __restrict__ fc1_b,
                      const float* __restrict__ fc2_W, const float* __restrict__ fc2_b,
                      const float* __restrict__ out_W, const float* __restrict__ out_b,
                      float* __restrict__ props) {
    __shared__ float s_W[64*64];
    __shared__ float s_v[64];
    __shared__ float s_red[64];
    int b = blockIdx.x, j = threadIdx.x;

    s_v[j] = g_pooled[b*64 + j];
    for (int i = j; i < 4096; i += 64) s_W[i] = fc1_W[i];
    __syncthreads();
    float acc = fc1_b[j];
    for (int k = 0; k < 64; k++) acc += s_v[k] * s_W[j*64 + k];
    float z1 = softplus_f(acc);
    __syncthreads();
    s_v[j] = z1;
    for (int i = j; i < 4096; i += 64) s_W[i] = fc2_W[i];
    __syncthreads();
    acc = fc2_b[j];
    for (int k = 0; k < 64; k++) acc += s_v[k] * s_W[j*64 + k];
    float z2 = softplus_f(acc);
    s_red[j] = z2 * out_W[j];
    __syncthreads();
    for (int s = 32; s > 0; s >>= 1) {
        if (j < s) s_red[j] += s_red[j + s];
        __syncthreads();
    }
    if (j == 0) props[b] = s_red[0] + out_b[0];
}

// ---------------- launch ----------------
extern "C" void kernel_launch(void* const* d_in, const int* in_sizes, int n_in,
                              void* d_out, int out_size) {
    const float* atom_fea = (const float*)d_in[0];
    const float* nbr_fea  = (const float*)d_in[1];
    const int*   nbr_idx  = (const int*)d_in[2];
    const int*   cai      = (const int*)d_in[3];
    const float* mask     = (const float*)d_in[4];
    const float* emb_W    = (const float*)d_in[5];
    const float* conv_W   = (const float*)d_in[6];
    const float* conv_b   = (const float*)d_in[7];
    const float* bn1_g    = (const float*)d_in[8];
    const float* bn1_b    = (const float*)d_in[9];
    const float* bn2_g    = (const float*)d_in[10];
    const float* bn2_b    = (const float*)d_in[11];
    const float* fc1_W    = (const float*)d_in[12];
    const float* fc1_b    = (const float*)d_in[13];
    const float* fc2_W    = (const float*)d_in[14];
    const float* fc2_b    = (const float*)d_in[15];
    const float* out_W    = (const float*)d_in[16];
    const float* out_b    = (const float*)d_in[17];
    float* out = (float*)d_out;

    float* st1; cudaGetSymbolAddress((void**)&st1, g_stats1);
    float* st2; cudaGetSymbolAddress((void**)&st2, g_stats2);
    uint32_t* bfc; cudaGetSymbolAddress((void**)&bfc, g_BfC);
    uint32_t* bfp; cudaGetSymbolAddress((void**)&bfp, g_BfP);

    k_prepw_all<<<(NCONV*(3072+8192) + 255)/256, 256>>>(conv_W);
    k_cvt_nbr<<<(int)(((size_t)(NM+128)*48 + 255)/256), 256>>>(nbr_fea);
    k_embed<<<(NATOM + 63)/64, 256>>>(atom_fea, mask, emb_W, out + BCRY);

    for (int l = 0; l < NCONV; l++) {
        k_pre_mma<<<dim3((NATOM + 127)/128, 2), 512>>>(bfp + l*8192);
        k_conv_mma<<<(NM + 127)/128, 256>>>(nbr_idx, conv_b + l*128, bfc + l*3072, st1 + l*256);
        k_act<<<NATOM/8, 256>>>(bn1_g + l*128, bn1_b + l*128, st1 + l*256, st2 + l*128);
        k_update<<<NATOM*64/256, 256>>>(bn2_g + l*64, bn2_b + l*64, st2 + l*128, (l == NCONV-1) ? 1 : 0);
    }

    k_pool<<<BCRY, 64>>>(cai);
    k_mlp<<<BCRY, 64>>>(fc1_W, fc1_b, fc2_W, fc2_b, out_W, out_b, out);
}

// round 15
// speedup vs baseline: 1.0459x; 1.0459x over previous
#include <cuda_runtime.h>
#include <cuda_bf16.h>
#include <math.h>
#include <stdint.h>

#define NATOM 50000
#define MNBR  12
#define AF    64
#define NBRF  41
#define ORIG  92
#define NCONV 3
#define NM    (NATOM*MNBR)
#define BCRY  500
#define NACRY 100
#define BN_EPS 1e-5f

// ---------------- scratch ----------------
static __device__ float g_h[NATOM*AF];
static __device__ __nv_bfloat16 g_hbf[NATOM*AF];
static __device__ __nv_bfloat16 g_CHb[NATOM*256];
static __device__ __nv_bfloat16 g_gatedb[(size_t)NM*128];
static __device__ float g_summed[NATOM*AF];
static __device__ uint32_t g_BfC[NCONV*3072];
static __device__ uint32_t g_BfP[NCONV*8192];
static __device__ float g_stats1[NCONV*256];
static __device__ float g_stats2[NCONV*128];
static __device__ float g_inv[NATOM];
static __device__ float g_pooled[BCRY*AF];

__device__ __forceinline__ float softplus_f(float x) {
    return fmaxf(x, 0.f) + log1pf(expf(-fabsf(x)));
}
__device__ __forceinline__ float sigmoid_f(float x) {
    return 1.f / (1.f + expf(-x));
}
__device__ __forceinline__ float softplus_fast(float x) {
    return fmaxf(x, 0.f) + __logf(1.f + __expf(-fabsf(x)));
}
__device__ __forceinline__ float sigmoid_fast(float x) {
    return 1.f / (1.f + __expf(-x));
}
__device__ __forceinline__ uint32_t packbf(float a, float b) {
    __nv_bfloat162 t = __floats2bfloat162_rn(a, b);
    return *reinterpret_cast<uint32_t*>(&t);
}
__device__ __forceinline__ void mma16816(float d[4], const uint32_t a[4], uint32_t b0, uint32_t b1) {
    asm volatile(
        "mma.sync.aligned.m16n8k16.row.col.f32.bf16.bf16.f32 "
        "{%0,%1,%2,%3},{%4,%5,%6,%7},{%8,%9},{%0,%1,%2,%3};\n"
        : "+f"(d[0]), "+f"(d[1]), "+f"(d[2]), "+f"(d[3])
        : "r"(a[0]), "r"(a[1]), "r"(a[2]), "r"(a[3]), "r"(b0), "r"(b1));
}

// ---------------- weights -> mma B-fragments + zero stats ----------------
__global__ void k_prepw_all(const float* __restrict__ Wbase) {
    int gidx = blockIdx.x * 256 + threadIdx.x;
    if (gidx < NCONV*256) g_stats1[gidx] = 0.f;
    if (gidx < NCONV*128) g_stats2[gidx] = 0.f;
    int per = 3072 + 8192;
    if (gidx >= NCONV*per) return;
    int l = gidx / per;
    int idx = gidx % per;
    const float* W = Wbase + (size_t)l*128*169;
    if (idx < 3072) {
        int r = idx & 1, ln = (idx >> 1) & 31, t = (idx >> 6) & 15, s = idx >> 10;
        int gid = ln >> 2, tig = ln & 3;
        int n = t*8 + gid;
        int k0 = s*16 + tig*2 + (r ? 8 : 0);
        float w0 = (k0   < 41) ? W[n*169 + 128 + k0]   : 0.f;
        float w1 = (k0+1 < 41) ? W[n*169 + 128 + k0+1] : 0.f;
        g_BfC[l*3072 + idx] = packbf(w0, w1);
    } else {
        int i2 = idx - 3072;
        int r = i2 & 1, ln = (i2 >> 1) & 31, t = (i2 >> 6) & 15, s = (i2 >> 10) & 3, cy = i2 >> 12;
        int gid = ln >> 2, tig = ln & 3;
        int n = cy*128 + t*8 + gid;
        int k0 = s*16 + tig*2 + (r ? 8 : 0);
        float w0, w1;
        if (n < 128) { w0 = W[n*169 + k0]; w1 = W[n*169 + k0 + 1]; }
        else         { w0 = W[(n-128)*169 + 64 + k0]; w1 = W[(n-128)*169 + 64 + k0 + 1]; }
        g_BfP[l*8192 + i2] = packbf(w0, w1);
    }
}

// ---------------- embedding (vectorized load/mask/store) ----------------
__global__ void k_embed(const float* __restrict__ atom_fea,
                        const float* __restrict__ mask,
                        const float* __restrict__ embW,
                        float* __restrict__ out_masked) {
    __shared__ float s_x[64][93];
    __shared__ float s_WT[92][64];
    __shared__ float4 s_mask4[23];
    int r0 = blockIdx.x * 64;
    int tid = threadIdx.x;
    int nrows = NATOM - r0; if (nrows > 64) nrows = 64;

    if (tid < 23) s_mask4[tid] = ((const float4*)mask)[tid];
    for (int i = tid; i < 92*64; i += 256) { int o = i / 92, k = i % 92; s_WT[k][o] = embW[i]; }
    __syncthreads();

    const float4* af4 = (const float4*)atom_fea;
    float4* om4 = (float4*)out_masked;
    for (int i = tid; i < nrows*23; i += 256) {
        int rr = i / 23, c = i % 23;
        float4 x = af4[(size_t)(r0+rr)*23 + c];
        float4 m = s_mask4[c];
        x.x *= m.x; x.y *= m.y; x.z *= m.z; x.w *= m.w;
        om4[(size_t)(r0+rr)*23 + c] = x;
        int k = c*4;
        s_x[rr][k] = x.x; s_x[rr][k+1] = x.y; s_x[rr][k+2] = x.z; s_x[rr][k+3] = x.w;
    }
    __syncthreads();

    int ty = tid / 16, tx = tid % 16;
    float acc[4][4] = {};
    for (int k = 0; k < 92; k++) {
        float b0 = s_WT[k][tx*4+0], b1 = s_WT[k][tx*4+1];
        float b2 = s_WT[k][tx*4+2], b3 = s_WT[k][tx*4+3];
        #pragma unroll
        for (int i = 0; i < 4; i++) {
            float a = s_x[ty*4+i][k];
            acc[i][0] += a*b0; acc[i][1] += a*b1; acc[i][2] += a*b2; acc[i][3] += a*b3;
        }
    }
    #pragma unroll
    for (int i = 0; i < 4; i++) {
        int r = r0 + ty*4 + i;
        if (r < NATOM) {
            #pragma unroll
            for (int j = 0; j < 4; j++) {
                g_h[r*64 + tx*4 + j] = acc[i][j];
                g_hbf[r*64 + tx*4 + j] = __float2bfloat16(acc[i][j]);
            }
        }
    }
}

// ---------------- CH = h @ [Wc^T | Wn^T], 512 threads (R12-proven) ----------------
__global__ __launch_bounds__(512, 2) void k_pre_mma(const uint32_t* __restrict__ BfP) {
    __shared__ __align__(16) unsigned char s_u[34816];
    __nv_bfloat16 (*s_A)[72] = (__nv_bfloat16(*)[72])s_u;
    uint32_t* s_Bf = (uint32_t*)(s_u + 18432);
    __nv_bfloat16 (*s_D)[136] = (__nv_bfloat16(*)[136])s_u;

    int r0 = blockIdx.x * 128;
    int cy = blockIdx.y;
    int tid = threadIdx.x;
    int nvalid = NATOM - r0; if (nvalid > 128) nvalid = 128;

    for (int i = tid; i < 4608; i += 512) ((uint32_t*)s_u)[i] = 0;
    __syncthreads();
    for (int i = tid; i < nvalid*32; i += 512) {
        int row = i >> 5, kk = i & 31;
        ((uint32_t*)s_u)[row*36 + kk] = ((const uint32_t*)g_hbf)[(size_t)(r0+row)*32 + kk];
    }
    for (int i = tid; i < 4096; i += 512) s_Bf[i] = BfP[cy*4096 + i];
    __syncthreads();

    int wid = tid >> 5, lane = tid & 31, gid = lane >> 2, tig = lane & 3;
    int wm = wid & 3, wn = wid >> 2;
    float acc[2][4][4];
    #pragma unroll
    for (int mt = 0; mt < 2; mt++)
        #pragma unroll
        for (int t = 0; t < 4; t++)
            #pragma unroll
            for (int j = 0; j < 4; j++) acc[mt][t][j] = 0.f;

    #pragma unroll
    for (int s = 0; s < 4; s++) {
        uint32_t a[2][4];
        #pragma unroll
        for (int mt = 0; mt < 2; mt++) {
            int row = wm*32 + mt*16 + gid;
            int kb = s*16 + 2*tig;
            a[mt][0] = *(const uint32_t*)&s_A[row][kb];
            a[mt][1] = *(const uint32_t*)&s_A[row+8][kb];
            a[mt][2] = *(const uint32_t*)&s_A[row][kb+8];
            a[mt][3] = *(const uint32_t*)&s_A[row+8][kb+8];
        }
        #pragma unroll
        for (int t = 0; t < 4; t++) {
            int gt = wn*4 + t;
            uint32_t b0 = s_Bf[((s*16+gt)*32+lane)*2];
            uint32_t b1 = s_Bf[((s*16+gt)*32+lane)*2 + 1];
            mma16816(acc[0][t], a[0], b0, b1);
            mma16816(acc[1][t], a[1], b0, b1);
        }
    }
    __syncthreads();
    #pragma unroll
    for (int mt = 0; mt < 2; mt++)
        #pragma unroll
        for (int t = 0; t < 4; t++) {
            int row = wm*32 + mt*16 + gid;
            int col = wn*32 + t*8 + 2*tig;
            *(uint32_t*)&s_D[row][col]   = packbf(acc[mt][t][0], acc[mt][t][1]);
            *(uint32_t*)&s_D[row+8][col] = packbf(acc[mt][t][2], acc[mt][t][3]);
        }
    __syncthreads();

    int ty = tid >> 4, tx = tid & 15;
    #pragma unroll
    for (int i = 0; i < 4; i++) {
        int r = ty*4 + i;
        if (r0 + r < NATOM)
            *(uint4*)&g_CHb[(size_t)(r0+r)*256 + cy*128 + tx*8] = *(const uint4*)&s_D[r][tx*8];
    }
}

// ---------------- main conv: R12-proven + vectorized s_D epilogue reads ----------------
__global__ __launch_bounds__(256, 2) void k_conv_mma(const float* __restrict__ nbr_fea,
                                                     const int*   __restrict__ nbr_idx,
                                                     const float* __restrict__ bias,
                                                     const uint32_t* __restrict__ BfC,
                                                     float* __restrict__ stats1) {
    __shared__ __align__(16) unsigned char s_u[34816];
    __nv_bfloat16 (*s_A)[56] = (__nv_bfloat16(*)[56])s_u;      // 128 x 56 bf16
    uint32_t* s_Bf = (uint32_t*)(s_u + 14336);                  // 3072 words
    __nv_bfloat16 (*s_D)[136] = (__nv_bfloat16(*)[136])s_u;     // reuse after mma
    __shared__ __align__(16) __nv_bfloat16 s_cc[12][128];
    __shared__ int   s_n[128], s_nbr[128];
    __shared__ float s_sum[128], s_sq[128], s_bias[128];

    int r0 = blockIdx.x * 128;
    int a0 = r0 / 12;
    int tid = threadIdx.x;
    int nvalid = NM - r0; if (nvalid > 128) nvalid = 128;

    for (int i = tid; i < 3584; i += 256) ((uint32_t*)s_u)[i] = 0;
    __syncthreads();
    {
        const float4* src = (const float4*)(nbr_fea + (size_t)r0*41);
        int nvec = nvalid*41/4;
        for (int i = tid; i < nvec; i += 256) {
            float4 v = src[i];
            int b = i*4;
            s_A[b/41][b%41]         = __float2bfloat16(v.x);
            s_A[(b+1)/41][(b+1)%41] = __float2bfloat16(v.y);
            s_A[(b+2)/41][(b+2)%41] = __float2bfloat16(v.z);
            s_A[(b+3)/41][(b+3)%41] = __float2bfloat16(v.w);
        }
    }
    for (int i = tid; i < 3072; i += 256) s_Bf[i] = BfC[i];
    for (int i = tid; i < 12*16; i += 256) {
        int row = i >> 4, c = i & 15;
        int atom = a0 + row; if (atom > NATOM-1) atom = NATOM-1;
        *(uint4*)&s_cc[row][c*8] = *(const uint4*)&g_CHb[(size_t)atom*256 + c*8];
    }
    if (tid < 128) {
        int e = r0 + tid;
        s_nbr[tid] = (e < NM) ? nbr_idx[e] : 0;
        s_n[tid]   = (e < NM) ? e / 12 - a0 : 0;
        s_sum[tid] = 0.f; s_sq[tid] = 0.f; s_bias[tid] = bias[tid];
    }
    __syncthreads();

    int wid = tid >> 5, lane = tid & 31, gid = lane >> 2, tig = lane & 3;
    int wm = wid & 3, wn = wid >> 2;
    float acc[2][8][4];
    #pragma unroll
    for (int mt = 0; mt < 2; mt++)
        #pragma unroll
        for (int t = 0; t < 8; t++)
            #pragma unroll
            for (int j = 0; j < 4; j++) acc[mt][t][j] = 0.f;

    #pragma unroll
    for (int s = 0; s < 3; s++) {
        uint32_t a[2][4];
        #pragma unroll
        for (int mt = 0; mt < 2; mt++) {
            int row = wm*32 + mt*16 + gid;
            int kb = s*16 + 2*tig;
            a[mt][0] = *(const uint32_t*)&s_A[row][kb];
            a[mt][1] = *(const uint32_t*)&s_A[row+8][kb];
            a[mt][2] = *(const uint32_t*)&s_A[row][kb+8];
            a[mt][3] = *(const uint32_t*)&s_A[row+8][kb+8];
        }
        #pragma unroll
        for (int t = 0; t < 8; t++) {
            int gt = wn*8 + t;
            uint32_t b0 = s_Bf[((s*16+gt)*32+lane)*2];
            uint32_t b1 = s_Bf[((s*16+gt)*32+lane)*2 + 1];
            mma16816(acc[0][t], a[0], b0, b1);
            mma16816(acc[1][t], a[1], b0, b1);
        }
    }
    __syncthreads();
    #pragma unroll
    for (int mt = 0; mt < 2; mt++)
        #pragma unroll
        for (int t = 0; t < 8; t++) {
            int row = wm*32 + mt*16 + gid;
            int col = wn*64 + t*8 + 2*tig;
            *(uint32_t*)&s_D[row][col]   = packbf(acc[mt][t][0], acc[mt][t][1]);
            *(uint32_t*)&s_D[row+8][col] = packbf(acc[mt][t][2], acc[mt][t][3]);
        }
    __syncthreads();

    int ty = tid >> 4, tx = tid & 15;
    float bs[8], cs[8], cq[8];
    #pragma unroll
    for (int j = 0; j < 8; j++) { bs[j] = s_bias[tx*8 + j]; cs[j] = 0.f; cq[j] = 0.f; }

    uint4 cn4[8];
    #pragma unroll
    for (int i = 0; i < 8; i++) {
        int lr = ty*8 + i;
        cn4[i] = *(const uint4*)&g_CHb[(size_t)s_nbr[lr]*256 + 128 + tx*8];
    }
    #pragma unroll
    for (int i = 0; i < 8; i++) {
        int lr = ty*8 + i;
        int e = r0 + lr;
        if (e < NM) {
            uint4 cc4 = *(const uint4*)&s_cc[s_n[lr]][tx*8];
            uint4 dd4 = *(const uint4*)&s_D[lr][tx*8];
            const uint32_t* ccw = (const uint32_t*)&cc4;
            const uint32_t* cnw = (const uint32_t*)&cn4[i];
            const uint32_t* ddw = (const uint32_t*)&dd4;
            uint32_t o[4];
            #pragma unroll
            for (int jj = 0; jj < 4; jj++) {
                float2 d2 = __bfloat1622float2(*(const __nv_bfloat162*)&ddw[jj]);
                float2 c2 = __bfloat1622float2(*(const __nv_bfloat162*)&ccw[jj]);
                float2 n2 = __bfloat1622float2(*(const __nv_bfloat162*)&cnw[jj]);
                float v0 = d2.x + c2.x + n2.x + bs[2*jj];
                float v1 = d2.y + c2.y + n2.y + bs[2*jj+1];
                cs[2*jj]   += v0; cq[2*jj]   += v0*v0;
                cs[2*jj+1] += v1; cq[2*jj+1] += v1*v1;
                o[jj] = packbf(v0, v1);
            }
            *(uint4*)&g_gatedb[(size_t)e*128 + tx*8] = make_uint4(o[0], o[1], o[2], o[3]);
        }
    }
    #pragma unroll
    for (int j = 0; j < 8; j++) {
        atomicAdd(&s_sum[tx*8+j], cs[j]);
        atomicAdd(&s_sq[tx*8+j],  cq[j]);
    }
    __syncthreads();
    if (tid < 128) {
        atomicAdd(&stats1[tid],       s_sum[tid]);
        atomicAdd(&stats1[128 + tid], s_sq[tid]);
    }
}

// ---------------- BN1-apply + activation + sum over M + BN2 stats ----------------
__global__ void k_act(const float* __restrict__ g1, const float* __restrict__ b1,
                      const float* __restrict__ stats1, float* __restrict__ stats2) {
    __shared__ float s_bnp[256];
    __shared__ float s_s[64], s_q[64];
    int tid = threadIdx.x;
    int lane = tid & 31;
    int an = blockIdx.x*8 + (tid >> 5);
    if (tid < 64) { s_s[tid] = 0.f; s_q[tid] = 0.f; }
    if (tid < 128) {
        float s = stats1[tid], q = stats1[128+tid];
        float inv = 1.f / (float)NM;
        float mu = s * inv;
        float var = q * inv - mu*mu;
        float a = g1[tid] * rsqrtf(var + BN_EPS);
        s_bnp[tid] = a;
        s_bnp[128+tid] = b1[tid] - mu*a;
    }
    __syncthreads();

    float2 af = *(const float2*)&s_bnp[2*lane];
    float2 ac = *(const float2*)&s_bnp[64 + 2*lane];
    float2 cf = *(const float2*)&s_bnp[128 + 2*lane];
    float2 cc = *(const float2*)&s_bnp[192 + 2*lane];
    const __nv_bfloat162* gp = (const __nv_bfloat162*)&g_gatedb[(size_t)an*1536];
    float sx = 0.f, sy = 0.f;
    #pragma unroll
    for (int m = 0; m < 12; m++) {
        float2 f = __bfloat1622float2(gp[m*64 + lane]);
        float2 c = __bfloat1622float2(gp[m*64 + 32 + lane]);
        sx += sigmoid_fast(af.x*f.x + cf.x) * softplus_fast(ac.x*c.x + cc.x);
        sy += sigmoid_fast(af.y*f.y + cf.y) * softplus_fast(ac.y*c.y + cc.y);
    }
    *(float2*)&g_summed[(size_t)an*64 + 2*lane] = make_float2(sx, sy);
    atomicAdd(&s_s[2*lane],   sx);
    atomicAdd(&s_s[2*lane+1], sy);
    atomicAdd(&s_q[2*lane],   sx*sx);
    atomicAdd(&s_q[2*lane+1], sy*sy);
    __syncthreads();
    if (tid < 64) {
        atomicAdd(&stats2[tid],      s_s[tid]);
        atomicAdd(&stats2[64 + tid], s_q[tid]);
    }
}

// ---------------- residual + softplus (+ optional fused norm) ----------------
__global__ void k_update(const float* __restrict__ g2, const float* __restrict__ b2,
                         const float* __restrict__ stats2, int do_norm) {
    __shared__ float s_bnp[128];
    __shared__ float s_nrm[4];
    int tid = threadIdx.x;
    if (tid < 64) {
        float s = stats2[tid], q = stats2[64+tid];
        float inv = 1.f / (float)NATOM;
        float mu = s * inv;
        float var = q * inv - mu*mu;
        float a = g2[tid] * rsqrtf(var + BN_EPS);
        s_bnp[tid] = a;
        s_bnp[64+tid] = b2[tid] - mu*a;
    }
    if (tid < 4) s_nrm[tid] = 0.f;
    __syncthreads();
    int idx = blockIdx.x*256 + tid;
    int j = idx & 63;
    float v = g_h[idx] + s_bnp[j]*g_summed[idx] + s_bnp[64+j];
    float r = softplus_f(v);
    g_h[idx] = r;
    g_hbf[idx] = __float2bfloat16(r);
    if (do_norm) {
        float ss = r*r;
        #pragma unroll
        for (int off = 16; off; off >>= 1) ss += __shfl_xor_sync(0xffffffffu, ss, off);
        int la = tid >> 6;
        if ((tid & 31) == 0) atomicAdd(&s_nrm[la], ss);
        __syncthreads();
        if ((tid & 63) == 0) {
            int n = idx >> 6;
            g_inv[n] = 1.f / fmaxf(sqrtf(s_nrm[la]), 1e-12f);
        }
    }
}

// ---------------- crystal pooling ----------------
__global__ void k_pool(const int* __restrict__ cai) {
    int b = blockIdx.x, j = threadIdx.x;
    float s = 0.f;
    for (int a = 0; a < NACRY; a++) {
        int idx = cai[b*NACRY + a];
        s += g_h[(size_t)idx*64 + j] * g_inv[idx];
    }
    g_pooled[b*64 + j] = s * (1.f / (float)NACRY);
}

// ---------------- final MLP ----------------
__global__ void k_mlp(const float* __restrict__ fc1_W, const float* __restrict__ fc1_b,
                      const float* __restrict__ fc2_W, const float* __restrict__ fc2_b,
                      const float* __restrict__ out_W, const float* __restrict__ out_b,
                      float* __restrict__ props) {
    __shared__ float s_W[64*64];
    __shared__ float s_v[64];
    __shared__ float s_red[64];
    int b = blockIdx.x, j = threadIdx.x;

    s_v[j] = g_pooled[b*64 + j];
    for (int i = j; i < 4096; i += 64) s_W[i] = fc1_W[i];
    __syncthreads();
    float acc = fc1_b[j];
    for (int k = 0; k < 64; k++) acc += s_v[k] * s_W[j*64 + k];
    float z1 = softplus_f(acc);
    __syncthreads();
    s_v[j] = z1;
    for (int i = j; i < 4096; i += 64) s_W[i] = fc2_W[i];
    __syncthreads();
    acc = fc2_b[j];
    for (int k = 0; k < 64; k++) acc += s_v[k] * s_W[j*64 + k];
    float z2 = softplus_f(acc);
    s_red[j] = z2 * out_W[j];
    __syncthreads();
    for (int s = 32; s > 0; s >>= 1) {
        if (j < s) s_red[j] += s_red[j + s];
        __syncthreads();
    }
    if (j == 0) props[b] = s_red[0] + out_b[0];
}

// ---------------- launch ----------------
extern "C" void kernel_launch(void* const* d_in, const int* in_sizes, int n_in,
                              void* d_out, int out_size) {
    const float* atom_fea = (const float*)d_in[0];
    const float* nbr_fea  = (const float*)d_in[1];
    const int*   nbr_idx  = (const int*)d_in[2];
    const int*   cai      = (const int*)d_in[3];
    const float* mask     = (const float*)d_in[4];
    const float* emb_W    = (const float*)d_in[5];
    const float* conv_W   = (const float*)d_in[6];
    const float* conv_b   = (const float*)d_in[7];
    const float* bn1_g    = (const float*)d_in[8];
    const float* bn1_b    = (const float*)d_in[9];
    const float* bn2_g    = (const float*)d_in[10];
    const float* bn2_b    = (const float*)d_in[11];
    const float* fc1_W    = (const float*)d_in[12];
    const float* fc1_b    = (const float*)d_in[13];
    const float* fc2_W    = (const float*)d_in[14];
    const float* fc2_b    = (const float*)d_in[15];
    const float* out_W    = (const float*)d_in[16];
    const float* out_b    = (const float*)d_in[17];
    float* out = (float*)d_out;

    float* st1; cudaGetSymbolAddress((void**)&st1, g_stats1);
    float* st2; cudaGetSymbolAddress((void**)&st2, g_stats2);
    uint32_t* bfc; cudaGetSymbolAddress((void**)&bfc, g_BfC);
    uint32_t* bfp; cudaGetSymbolAddress((void**)&bfp, g_BfP);

    k_prepw_all<<<(NCONV*(3072+8192) + 255)/256, 256>>>(conv_W);
    k_embed<<<(NATOM + 63)/64, 256>>>(atom_fea, mask, emb_W, out + BCRY);

    for (int l = 0; l < NCONV; l++) {
        k_pre_mma<<<dim3((NATOM + 127)/128, 2), 512>>>(bfp + l*8192);
        k_conv_mma<<<(NM + 127)/128, 256>>>(nbr_fea, nbr_idx, conv_b + l*128, bfc + l*3072, st1 + l*256);
        k_act<<<NATOM/8, 256>>>(bn1_g + l*128, bn1_b + l*128, st1 + l*256, st2 + l*128);
        k_update<<<NATOM*64/256, 256>>>(bn2_g + l*64, bn2_b + l*64, st2 + l*128, (l == NCONV-1) ? 1 : 0);
    }

    k_pool<<<BCRY, 64>>>(cai);
    k_mlp<<<BCRY, 64>>>(fc1_W, fc1_b, fc2_W, fc2_b, out_W, out_b, out);
}

// round 16
// speedup vs baseline: 1.1395x; 1.0895x over previous
#include <cuda_runtime.h>
#include <cuda_bf16.h>
#include <math.h>
#include <stdint.h>

#define NATOM 50000
#define MNBR  12
#define AF    64
#define NBRF  41
#define ORIG  92
#define NCONV 3
#define NM    (NATOM*MNBR)
#define BCRY  500
#define NACRY 100
#define BN_EPS 1e-5f

// ---------------- scratch ----------------
static __device__ float g_h[NATOM*AF];
static __device__ __nv_bfloat16 g_hbf[NATOM*AF];
static __device__ __nv_bfloat16 g_CHb[NATOM*256];
static __device__ __nv_bfloat16 g_gatedb[(size_t)NM*128];
static __device__ float g_summed[NATOM*AF];
static __device__ uint32_t g_BfC[NCONV*3072];
static __device__ uint32_t g_BfP[NCONV*8192];
static __device__ float g_stats1[NCONV*256];
static __device__ float g_stats2[NCONV*128];
static __device__ float g_inv[NATOM];
static __device__ float g_pooled[BCRY*AF];

__device__ __forceinline__ float softplus_f(float x) {
    return fmaxf(x, 0.f) + log1pf(expf(-fabsf(x)));
}
__device__ __forceinline__ float softplus_fast(float x) {
    return fmaxf(x, 0.f) + __logf(1.f + __expf(-fabsf(x)));
}
// HW tanh (sm_75+): 1 MUFU op; sigmoid = 0.5*tanh(x/2)+0.5
__device__ __forceinline__ float sigmoid_tanh(float x) {
    float t;
    asm("tanh.approx.f32 %0, %1;" : "=f"(t) : "f"(x * 0.5f));
    return fmaf(t, 0.5f, 0.5f);
}
__device__ __forceinline__ uint32_t packbf(float a, float b) {
    __nv_bfloat162 t = __floats2bfloat162_rn(a, b);
    return *reinterpret_cast<uint32_t*>(&t);
}
__device__ __forceinline__ void mma16816(float d[4], const uint32_t a[4], uint32_t b0, uint32_t b1) {
    asm volatile(
        "mma.sync.aligned.m16n8k16.row.col.f32.bf16.bf16.f32 "
        "{%0,%1,%2,%3},{%4,%5,%6,%7},{%8,%9},{%0,%1,%2,%3};\n"
        : "+f"(d[0]), "+f"(d[1]), "+f"(d[2]), "+f"(d[3])
        : "r"(a[0]), "r"(a[1]), "r"(a[2]), "r"(a[3]), "r"(b0), "r"(b1));
}

// ---------------- weights -> mma B-fragments + zero stats ----------------
__global__ void k_prepw_all(const float* __restrict__ Wbase) {
    int gidx = blockIdx.x * 256 + threadIdx.x;
    if (gidx < NCONV*256) g_stats1[gidx] = 0.f;
    if (gidx < NCONV*128) g_stats2[gidx] = 0.f;
    int per = 3072 + 8192;
    if (gidx >= NCONV*per) return;
    int l = gidx / per;
    int idx = gidx % per;
    const float* W = Wbase + (size_t)l*128*169;
    if (idx < 3072) {
        int r = idx & 1, ln = (idx >> 1) & 31, t = (idx >> 6) & 15, s = idx >> 10;
        int gid = ln >> 2, tig = ln & 3;
        int n = t*8 + gid;
        int k0 = s*16 + tig*2 + (r ? 8 : 0);
        float w0 = (k0   < 41) ? W[n*169 + 128 + k0]   : 0.f;
        float w1 = (k0+1 < 41) ? W[n*169 + 128 + k0+1] : 0.f;
        g_BfC[l*3072 + idx] = packbf(w0, w1);
    } else {
        int i2 = idx - 3072;
        int r = i2 & 1, ln = (i2 >> 1) & 31, t = (i2 >> 6) & 15, s = (i2 >> 10) & 3, cy = i2 >> 12;
        int gid = ln >> 2, tig = ln & 3;
        int n = cy*128 + t*8 + gid;
        int k0 = s*16 + tig*2 + (r ? 8 : 0);
        float w0, w1;
        if (n < 128) { w0 = W[n*169 + k0]; w1 = W[n*169 + k0 + 1]; }
        else         { w0 = W[(n-128)*169 + 64 + k0]; w1 = W[(n-128)*169 + 64 + k0 + 1]; }
        g_BfP[l*8192 + i2] = packbf(w0, w1);
    }
}

// ---------------- embedding (R12-proven) ----------------
__global__ void k_embed(const float* __restrict__ atom_fea,
                        const float* __restrict__ mask,
                        const float* __restrict__ embW,
                        float* __restrict__ out_masked) {
    __shared__ float s_x[64][93];
    __shared__ float s_WT[92][64];
    int r0 = blockIdx.x * 64;
    int tid = threadIdx.x;
    int nrows = NATOM - r0; if (nrows > 64) nrows = 64;

    for (int i = tid; i < 92*64; i += 256) { int o = i / 92, k = i % 92; s_WT[k][o] = embW[i]; }
    for (int i = tid; i < nrows*92; i += 256) {
        int rr = i / 92, k = i % 92;
        float v = atom_fea[(size_t)(r0+rr)*92 + k] * mask[k];
        s_x[rr][k] = v;
        out_masked[(size_t)(r0+rr)*92 + k] = v;
    }
    __syncthreads();

    int ty = tid / 16, tx = tid % 16;
    float acc[4][4] = {};
    for (int k = 0; k < 92; k++) {
        float b0 = s_WT[k][tx*4+0], b1 = s_WT[k][tx*4+1];
        float b2 = s_WT[k][tx*4+2], b3 = s_WT[k][tx*4+3];
        #pragma unroll
        for (int i = 0; i < 4; i++) {
            float a = s_x[ty*4+i][k];
            acc[i][0] += a*b0; acc[i][1] += a*b1; acc[i][2] += a*b2; acc[i][3] += a*b3;
        }
    }
    #pragma unroll
    for (int i = 0; i < 4; i++) {
        int r = r0 + ty*4 + i;
        if (r < NATOM) {
            #pragma unroll
            for (int j = 0; j < 4; j++) {
                g_h[r*64 + tx*4 + j] = acc[i][j];
                g_hbf[r*64 + tx*4 + j] = __float2bfloat16(acc[i][j]);
            }
        }
    }
}

// ---------------- CH = h @ [Wc^T | Wn^T], 512 threads (R12-proven) ----------------
__global__ __launch_bounds__(512, 2) void k_pre_mma(const uint32_t* __restrict__ BfP) {
    __shared__ __align__(16) unsigned char s_u[34816];
    __nv_bfloat16 (*s_A)[72] = (__nv_bfloat16(*)[72])s_u;
    uint32_t* s_Bf = (uint32_t*)(s_u + 18432);
    __nv_bfloat16 (*s_D)[136] = (__nv_bfloat16(*)[136])s_u;

    int r0 = blockIdx.x * 128;
    int cy = blockIdx.y;
    int tid = threadIdx.x;
    int nvalid = NATOM - r0; if (nvalid > 128) nvalid = 128;

    for (int i = tid; i < 4608; i += 512) ((uint32_t*)s_u)[i] = 0;
    __syncthreads();
    for (int i = tid; i < nvalid*32; i += 512) {
        int row = i >> 5, kk = i & 31;
        ((uint32_t*)s_u)[row*36 + kk] = ((const uint32_t*)g_hbf)[(size_t)(r0+row)*32 + kk];
    }
    for (int i = tid; i < 4096; i += 512) s_Bf[i] = BfP[cy*4096 + i];
    __syncthreads();

    int wid = tid >> 5, lane = tid & 31, gid = lane >> 2, tig = lane & 3;
    int wm = wid & 3, wn = wid >> 2;
    float acc[2][4][4];
    #pragma unroll
    for (int mt = 0; mt < 2; mt++)
        #pragma unroll
        for (int t = 0; t < 4; t++)
            #pragma unroll
            for (int j = 0; j < 4; j++) acc[mt][t][j] = 0.f;

    #pragma unroll
    for (int s = 0; s < 4; s++) {
        uint32_t a[2][4];
        #pragma unroll
        for (int mt = 0; mt < 2; mt++) {
            int row = wm*32 + mt*16 + gid;
            int kb = s*16 + 2*tig;
            a[mt][0] = *(const uint32_t*)&s_A[row][kb];
            a[mt][1] = *(const uint32_t*)&s_A[row+8][kb];
            a[mt][2] = *(const uint32_t*)&s_A[row][kb+8];
            a[mt][3] = *(const uint32_t*)&s_A[row+8][kb+8];
        }
        #pragma unroll
        for (int t = 0; t < 4; t++) {
            int gt = wn*4 + t;
            uint32_t b0 = s_Bf[((s*16+gt)*32+lane)*2];
            uint32_t b1 = s_Bf[((s*16+gt)*32+lane)*2 + 1];
            mma16816(acc[0][t], a[0], b0, b1);
            mma16816(acc[1][t], a[1], b0, b1);
        }
    }
    __syncthreads();
    #pragma unroll
    for (int mt = 0; mt < 2; mt++)
        #pragma unroll
        for (int t = 0; t < 4; t++) {
            int row = wm*32 + mt*16 + gid;
            int col = wn*32 + t*8 + 2*tig;
            *(uint32_t*)&s_D[row][col]   = packbf(acc[mt][t][0], acc[mt][t][1]);
            *(uint32_t*)&s_D[row+8][col] = packbf(acc[mt][t][2], acc[mt][t][3]);
        }
    __syncthreads();

    int ty = tid >> 4, tx = tid & 15;
    #pragma unroll
    for (int i = 0; i < 4; i++) {
        int r = ty*4 + i;
        if (r0 + r < NATOM)
            *(uint4*)&g_CHb[(size_t)(r0+r)*256 + cy*128 + tx*8] = *(const uint4*)&s_D[r][tx*8];
    }
}

// ---------------- main conv (R12-proven, untouched) ----------------
__global__ __launch_bounds__(256, 2) void k_conv_mma(const float* __restrict__ nbr_fea,
                                                     const int*   __restrict__ nbr_idx,
                                                     const float* __restrict__ bias,
                                                     const uint32_t* __restrict__ BfC,
                                                     float* __restrict__ stats1) {
    __shared__ __align__(16) unsigned char s_u[34816];
    __nv_bfloat16 (*s_A)[56] = (__nv_bfloat16(*)[56])s_u;
    uint32_t* s_Bf = (uint32_t*)(s_u + 14336);
    __nv_bfloat16 (*s_D)[136] = (__nv_bfloat16(*)[136])s_u;
    __shared__ __align__(16) __nv_bfloat16 s_cc[12][128];
    __shared__ int   s_n[128], s_nbr[128];
    __shared__ float s_sum[128], s_sq[128], s_bias[128];

    int r0 = blockIdx.x * 128;
    int a0 = r0 / 12;
    int tid = threadIdx.x;
    int nvalid = NM - r0; if (nvalid > 128) nvalid = 128;

    for (int i = tid; i < 3584; i += 256) ((uint32_t*)s_u)[i] = 0;
    __syncthreads();
    {
        const float4* src = (const float4*)(nbr_fea + (size_t)r0*41);
        int nvec = nvalid*41/4;
        for (int i = tid; i < nvec; i += 256) {
            float4 v = src[i];
            int b = i*4;
            s_A[b/41][b%41]         = __float2bfloat16(v.x);
            s_A[(b+1)/41][(b+1)%41] = __float2bfloat16(v.y);
            s_A[(b+2)/41][(b+2)%41] = __float2bfloat16(v.z);
            s_A[(b+3)/41][(b+3)%41] = __float2bfloat16(v.w);
        }
    }
    for (int i = tid; i < 3072; i += 256) s_Bf[i] = BfC[i];
    for (int i = tid; i < 12*16; i += 256) {
        int row = i >> 4, c = i & 15;
        int atom = a0 + row; if (atom > NATOM-1) atom = NATOM-1;
        *(uint4*)&s_cc[row][c*8] = *(const uint4*)&g_CHb[(size_t)atom*256 + c*8];
    }
    if (tid < 128) {
        int e = r0 + tid;
        s_nbr[tid] = (e < NM) ? nbr_idx[e] : 0;
        s_n[tid]   = (e < NM) ? e / 12 - a0 : 0;
        s_sum[tid] = 0.f; s_sq[tid] = 0.f; s_bias[tid] = bias[tid];
    }
    __syncthreads();

    int wid = tid >> 5, lane = tid & 31, gid = lane >> 2, tig = lane & 3;
    int wm = wid & 3, wn = wid >> 2;
    float acc[2][8][4];
    #pragma unroll
    for (int mt = 0; mt < 2; mt++)
        #pragma unroll
        for (int t = 0; t < 8; t++)
            #pragma unroll
            for (int j = 0; j < 4; j++) acc[mt][t][j] = 0.f;

    #pragma unroll
    for (int s = 0; s < 3; s++) {
        uint32_t a[2][4];
        #pragma unroll
        for (int mt = 0; mt < 2; mt++) {
            int row = wm*32 + mt*16 + gid;
            int kb = s*16 + 2*tig;
            a[mt][0] = *(const uint32_t*)&s_A[row][kb];
            a[mt][1] = *(const uint32_t*)&s_A[row+8][kb];
            a[mt][2] = *(const uint32_t*)&s_A[row][kb+8];
            a[mt][3] = *(const uint32_t*)&s_A[row+8][kb+8];
        }
        #pragma unroll
        for (int t = 0; t < 8; t++) {
            int gt = wn*8 + t;
            uint32_t b0 = s_Bf[((s*16+gt)*32+lane)*2];
            uint32_t b1 = s_Bf[((s*16+gt)*32+lane)*2 + 1];
            mma16816(acc[0][t], a[0], b0, b1);
            mma16816(acc[1][t], a[1], b0, b1);
        }
    }
    __syncthreads();
    #pragma unroll
    for (int mt = 0; mt < 2; mt++)
        #pragma unroll
        for (int t = 0; t < 8; t++) {
            int row = wm*32 + mt*16 + gid;
            int col = wn*64 + t*8 + 2*tig;
            *(uint32_t*)&s_D[row][col]   = packbf(acc[mt][t][0], acc[mt][t][1]);
            *(uint32_t*)&s_D[row+8][col] = packbf(acc[mt][t][2], acc[mt][t][3]);
        }
    __syncthreads();

    int ty = tid >> 4, tx = tid & 15;
    float bs[8], cs[8], cq[8];
    #pragma unroll
    for (int j = 0; j < 8; j++) { bs[j] = s_bias[tx*8 + j]; cs[j] = 0.f; cq[j] = 0.f; }

    uint4 cn4[8];
    #pragma unroll
    for (int i = 0; i < 8; i++) {
        int lr = ty*8 + i;
        cn4[i] = *(const uint4*)&g_CHb[(size_t)s_nbr[lr]*256 + 128 + tx*8];
    }
    #pragma unroll
    for (int i = 0; i < 8; i++) {
        int lr = ty*8 + i;
        int e = r0 + lr;
        if (e < NM) {
            uint4 cc4 = *(const uint4*)&s_cc[s_n[lr]][tx*8];
            const uint32_t* ccw = (const uint32_t*)&cc4;
            const uint32_t* cnw = (const uint32_t*)&cn4[i];
            const __nv_bfloat162* dd = (const __nv_bfloat162*)&s_D[lr][tx*8];
            uint32_t o[4];
            #pragma unroll
            for (int jj = 0; jj < 4; jj++) {
                float2 d2 = __bfloat1622float2(dd[jj]);
                float2 c2 = __bfloat1622float2(*(const __nv_bfloat162*)&ccw[jj]);
                float2 n2 = __bfloat1622float2(*(const __nv_bfloat162*)&cnw[jj]);
                float v0 = d2.x + c2.x + n2.x + bs[2*jj];
                float v1 = d2.y + c2.y + n2.y + bs[2*jj+1];
                cs[2*jj]   += v0; cq[2*jj]   += v0*v0;
                cs[2*jj+1] += v1; cq[2*jj+1] += v1*v1;
                o[jj] = packbf(v0, v1);
            }
            *(uint4*)&g_gatedb[(size_t)e*128 + tx*8] = make_uint4(o[0], o[1], o[2], o[3]);
        }
    }
    #pragma unroll
    for (int j = 0; j < 8; j++) {
        atomicAdd(&s_sum[tx*8+j], cs[j]);
        atomicAdd(&s_sq[tx*8+j],  cq[j]);
    }
    __syncthreads();
    if (tid < 128) {
        atomicAdd(&stats1[tid],       s_sum[tid]);
        atomicAdd(&stats1[128 + tid], s_sq[tid]);
    }
}

// ---------------- BN1-apply + activation (HW tanh sigmoid) + sum over M + BN2 stats ----------------
__global__ void k_act(const float* __restrict__ g1, const float* __restrict__ b1,
                      const float* __restrict__ stats1, float* __restrict__ stats2) {
    __shared__ float s_bnp[256];
    __shared__ float s_s[64], s_q[64];
    int tid = threadIdx.x;
    int lane = tid & 31;
    int an = blockIdx.x*8 + (tid >> 5);
    if (tid < 64) { s_s[tid] = 0.f; s_q[tid] = 0.f; }
    if (tid < 128) {
        float s = stats1[tid], q = stats1[128+tid];
        float inv = 1.f / (float)NM;
        float mu = s * inv;
        float var = q * inv - mu*mu;
        float a = g1[tid] * rsqrtf(var + BN_EPS);
        s_bnp[tid] = a;
        s_bnp[128+tid] = b1[tid] - mu*a;
    }
    __syncthreads();

    float2 af = *(const float2*)&s_bnp[2*lane];
    float2 ac = *(const float2*)&s_bnp[64 + 2*lane];
    float2 cf = *(const float2*)&s_bnp[128 + 2*lane];
    float2 cc = *(const float2*)&s_bnp[192 + 2*lane];
    const __nv_bfloat162* gp = (const __nv_bfloat162*)&g_gatedb[(size_t)an*1536];
    float sx = 0.f, sy = 0.f;
    #pragma unroll
    for (int m = 0; m < 12; m++) {
        float2 f = __bfloat1622float2(gp[m*64 + lane]);
        float2 c = __bfloat1622float2(gp[m*64 + 32 + lane]);
        sx += sigmoid_tanh(af.x*f.x + cf.x) * softplus_fast(ac.x*c.x + cc.x);
        sy += sigmoid_tanh(af.y*f.y + cf.y) * softplus_fast(ac.y*c.y + cc.y);
    }
    *(float2*)&g_summed[(size_t)an*64 + 2*lane] = make_float2(sx, sy);
    atomicAdd(&s_s[2*lane],   sx);
    atomicAdd(&s_s[2*lane+1], sy);
    atomicAdd(&s_q[2*lane],   sx*sx);
    atomicAdd(&s_q[2*lane+1], sy*sy);
    __syncthreads();
    if (tid < 64) {
        atomicAdd(&stats2[tid],      s_s[tid]);
        atomicAdd(&stats2[64 + tid], s_q[tid]);
    }
}

// ---------------- residual + softplus (+ optional fused norm) ----------------
__global__ void k_update(const float* __restrict__ g2, const float* __restrict__ b2,
                         const float* __restrict__ stats2, int do_norm) {
    __shared__ float s_bnp[128];
    __shared__ float s_nrm[4];
    int tid = threadIdx.x;
    if (tid < 64) {
        float s = stats2[tid], q = stats2[64+tid];
        float inv = 1.f / (float)NATOM;
        float mu = s * inv;
        float var = q * inv - mu*mu;
        float a = g2[tid] * rsqrtf(var + BN_EPS);
        s_bnp[tid] = a;
        s_bnp[64+tid] = b2[tid] - mu*a;
    }
    if (tid < 4) s_nrm[tid] = 0.f;
    __syncthreads();
    int idx = blockIdx.x*256 + tid;
    int j = idx & 63;
    float v = g_h[idx] + s_bnp[j]*g_summed[idx] + s_bnp[64+j];
    float r = softplus_f(v);
    g_h[idx] = r;
    g_hbf[idx] = __float2bfloat16(r);
    if (do_norm) {
        float ss = r*r;
        #pragma unroll
        for (int off = 16; off; off >>= 1) ss += __shfl_xor_sync(0xffffffffu, ss, off);
        int la = tid >> 6;
        if ((tid & 31) == 0) atomicAdd(&s_nrm[la], ss);
        __syncthreads();
        if ((tid & 63) == 0) {
            int n = idx >> 6;
            g_inv[n] = 1.f / fmaxf(sqrtf(s_nrm[la]), 1e-12f);
        }
    }
}

// ---------------- crystal pooling ----------------
__global__ void k_pool(const int* __restrict__ cai) {
    int b = blockIdx.x, j = threadIdx.x;
    float s = 0.f;
    for (int a = 0; a < NACRY; a++) {
        int idx = cai[b*NACRY + a];
        s += g_h[(size_t)idx*64 + j] * g_inv[idx];
    }
    g_pooled[b*64 + j] = s * (1.f / (float)NACRY);
}

// ---------------- final MLP ----------------
__global__ void k_mlp(const float* __restrict__ fc1_W, const float* __restrict__ fc1_b,
                      const float* __restrict__ fc2_W, const float* __restrict__ fc2_b,
                      const float* __restrict__ out_W, const float* __restrict__ out_b,
                      float* __restrict__ props) {
    __shared__ float s_W[64*64];
    __shared__ float s_v[64];
    __shared__ float s_red[64];
    int b = blockIdx.x, j = threadIdx.x;

    s_v[j] = g_pooled[b*64 + j];
    for (int i = j; i < 4096; i += 64) s_W[i] = fc1_W[i];
    __syncthreads();
    float acc = fc1_b[j];
    for (int k = 0; k < 64; k++) acc += s_v[k] * s_W[j*64 + k];
    float z1 = softplus_f(acc);
    __syncthreads();
    s_v[j] = z1;
    for (int i = j; i < 4096; i += 64) s_W[i] = fc2_W[i];
    __syncthreads();
    acc = fc2_b[j];
    for (int k = 0; k < 64; k++) acc += s_v[k] * s_W[j*64 + k];
    float z2 = softplus_f(acc);
    s_red[j] = z2 * out_W[j];
    __syncthreads();
    for (int s = 32; s > 0; s >>= 1) {
        if (j < s) s_red[j] += s_red[j + s];
        __syncthreads();
    }
    if (j == 0) props[b] = s_red[0] + out_b[0];
}

// ---------------- launch ----------------
extern "C" void kernel_launch(void* const* d_in, const int* in_sizes, int n_in,
                              void* d_out, int out_size) {
    const float* atom_fea = (const float*)d_in[0];
    const float* nbr_fea  = (const float*)d_in[1];
    const int*   nbr_idx  = (const int*)d_in[2];
    const int*   cai      = (const int*)d_in[3];
    const float* mask     = (const float*)d_in[4];
    const float* emb_W    = (const float*)d_in[5];
    const float* conv_W   = (const float*)d_in[6];
    const float* conv_b   = (const float*)d_in[7];
    const float* bn1_g    = (const float*)d_in[8];
    const float* bn1_b    = (const float*)d_in[9];
    const float* bn2_g    = (const float*)d_in[10];
    const float* bn2_b    = (const float*)d_in[11];
    const float* fc1_W    = (const float*)d_in[12];
    const float* fc1_b    = (const float*)d_in[13];
    const float* fc2_W    = (const float*)d_in[14];
    const float* fc2_b    = (const float*)d_in[15];
    const float* out_W    = (const float*)d_in[16];
    const float* out_b    = (const float*)d_in[17];
    float* out = (float*)d_out;

    float* st1; cudaGetSymbolAddress((void**)&st1, g_stats1);
    float* st2; cudaGetSymbolAddress((void**)&st2, g_stats2);
    uint32_t* bfc; cudaGetSymbolAddress((void**)&bfc, g_BfC);
    uint32_t* bfp; cudaGetSymbolAddress((void**)&bfp, g_BfP);

    k_prepw_all<<<(NCONV*(3072+8192) + 255)/256, 256>>>(conv_W);
    k_embed<<<(NATOM + 63)/64, 256>>>(atom_fea, mask, emb_W, out + BCRY);

    for (int l = 0; l < NCONV; l++) {
        k_pre_mma<<<dim3((NATOM + 127)/128, 2), 512>>>(bfp + l*8192);
        k_conv_mma<<<(NM + 127)/128, 256>>>(nbr_fea, nbr_idx, conv_b + l*128, bfc + l*3072, st1 + l*256);
        k_act<<<NATOM/8, 256>>>(bn1_g + l*128, bn1_b + l*128, st1 + l*256, st2 + l*128);
        k_update<<<NATOM*64/256, 256>>>(bn2_g + l*64, bn2_b + l*64, st2 + l*128, (l == NCONV-1) ? 1 : 0);
    }

    k_pool<<<BCRY, 64>>>(cai);
    k_mlp<<<BCRY, 64>>>(fc1_W, fc1_b, fc2_W, fc2_b, out_W, out_b, out);
}

// round 17
// speedup vs baseline: 1.1414x; 1.0017x over previous
#include <cuda_runtime.h>
#include <cuda_bf16.h>
#include <math.h>
#include <stdint.h>

#define NATOM 50000
#define MNBR  12
#define AF    64
#define NBRF  41
#define ORIG  92
#define NCONV 3
#define NM    (NATOM*MNBR)
#define BCRY  500
#define NACRY 100
#define BN_EPS 1e-5f

// ---------------- scratch ----------------
static __device__ float g_h[NATOM*AF];
static __device__ __nv_bfloat16 g_hbf[NATOM*AF];
static __device__ __nv_bfloat16 g_CHb[NATOM*256];
static __device__ __nv_bfloat16 g_gatedb[(size_t)NM*128];
static __device__ float g_summed[NATOM*AF];
static __device__ uint32_t g_BfC[NCONV*3072];
static __device__ uint32_t g_BfP[NCONV*8192];
static __device__ float g_stats1[NCONV*256];
static __device__ float g_stats2[NCONV*128];
static __device__ float g_inv[NATOM];
static __device__ float g_pooled[BCRY*AF];

__device__ __forceinline__ float softplus_f(float x) {
    return fmaxf(x, 0.f) + log1pf(expf(-fabsf(x)));
}
__device__ __forceinline__ float softplus_fast(float x) {
    return fmaxf(x, 0.f) + __logf(1.f + __expf(-fabsf(x)));
}
// HW tanh (sm_75+): 1 MUFU op; sigmoid = 0.5*tanh(x/2)+0.5
__device__ __forceinline__ float sigmoid_tanh(float x) {
    float t;
    asm("tanh.approx.f32 %0, %1;" : "=f"(t) : "f"(x * 0.5f));
    return fmaf(t, 0.5f, 0.5f);
}
__device__ __forceinline__ uint32_t packbf(float a, float b) {
    __nv_bfloat162 t = __floats2bfloat162_rn(a, b);
    return *reinterpret_cast<uint32_t*>(&t);
}
__device__ __forceinline__ void mma16816(float d[4], const uint32_t a[4], uint32_t b0, uint32_t b1) {
    asm volatile(
        "mma.sync.aligned.m16n8k16.row.col.f32.bf16.bf16.f32 "
        "{%0,%1,%2,%3},{%4,%5,%6,%7},{%8,%9},{%0,%1,%2,%3};\n"
        : "+f"(d[0]), "+f"(d[1]), "+f"(d[2]), "+f"(d[3])
        : "r"(a[0]), "r"(a[1]), "r"(a[2]), "r"(a[3]), "r"(b0), "r"(b1));
}

// ---------------- weights -> mma B-fragments + zero stats ----------------
__global__ void k_prepw_all(const float* __restrict__ Wbase) {
    int gidx = blockIdx.x * 256 + threadIdx.x;
    if (gidx < NCONV*256) g_stats1[gidx] = 0.f;
    if (gidx < NCONV*128) g_stats2[gidx] = 0.f;
    int per = 3072 + 8192;
    if (gidx >= NCONV*per) return;
    int l = gidx / per;
    int idx = gidx % per;
    const float* W = Wbase + (size_t)l*128*169;
    if (idx < 3072) {
        int r = idx & 1, ln = (idx >> 1) & 31, t = (idx >> 6) & 15, s = idx >> 10;
        int gid = ln >> 2, tig = ln & 3;
        int n = t*8 + gid;
        int k0 = s*16 + tig*2 + (r ? 8 : 0);
        float w0 = (k0   < 41) ? W[n*169 + 128 + k0]   : 0.f;
        float w1 = (k0+1 < 41) ? W[n*169 + 128 + k0+1] : 0.f;
        g_BfC[l*3072 + idx] = packbf(w0, w1);
    } else {
        int i2 = idx - 3072;
        int r = i2 & 1, ln = (i2 >> 1) & 31, t = (i2 >> 6) & 15, s = (i2 >> 10) & 3, cy = i2 >> 12;
        int gid = ln >> 2, tig = ln & 3;
        int n = cy*128 + t*8 + gid;
        int k0 = s*16 + tig*2 + (r ? 8 : 0);
        float w0, w1;
        if (n < 128) { w0 = W[n*169 + k0]; w1 = W[n*169 + k0 + 1]; }
        else         { w0 = W[(n-128)*169 + 64 + k0]; w1 = W[(n-128)*169 + 64 + k0 + 1]; }
        g_BfP[l*8192 + i2] = packbf(w0, w1);
    }
}

// ---------------- embedding: vectorized gmem I/O, scalar smem scatter ----------------
__global__ void k_embed(const float* __restrict__ atom_fea,
                        const float* __restrict__ mask,
                        const float* __restrict__ embW,
                        float* __restrict__ out_masked) {
    __shared__ float s_x[64][93];
    __shared__ float s_WT[92][64];
    __shared__ float4 s_mask4[23];
    int r0 = blockIdx.x * 64;
    int tid = threadIdx.x;
    int nrows = NATOM - r0; if (nrows > 64) nrows = 64;

    if (tid < 23) s_mask4[tid] = ((const float4*)mask)[tid];
    for (int i = tid; i < 92*64; i += 256) { int o = i / 92, k = i % 92; s_WT[k][o] = embW[i]; }
    __syncthreads();

    const float4* af4 = (const float4*)atom_fea;
    float4* om4 = (float4*)out_masked;
    for (int i = tid; i < nrows*23; i += 256) {
        int rr = i / 23, c = i % 23;
        float4 x = af4[(size_t)(r0+rr)*23 + c];
        float4 m = s_mask4[c];
        x.x *= m.x; x.y *= m.y; x.z *= m.z; x.w *= m.w;
        om4[(size_t)(r0+rr)*23 + c] = x;
        int k = c*4;
        s_x[rr][k] = x.x; s_x[rr][k+1] = x.y; s_x[rr][k+2] = x.z; s_x[rr][k+3] = x.w;
    }
    __syncthreads();

    int ty = tid / 16, tx = tid % 16;
    float acc[4][4] = {};
    for (int k = 0; k < 92; k++) {
        float b0 = s_WT[k][tx*4+0], b1 = s_WT[k][tx*4+1];
        float b2 = s_WT[k][tx*4+2], b3 = s_WT[k][tx*4+3];
        #pragma unroll
        for (int i = 0; i < 4; i++) {
            float a = s_x[ty*4+i][k];
            acc[i][0] += a*b0; acc[i][1] += a*b1; acc[i][2] += a*b2; acc[i][3] += a*b3;
        }
    }
    #pragma unroll
    for (int i = 0; i < 4; i++) {
        int r = r0 + ty*4 + i;
        if (r < NATOM) {
            #pragma unroll
            for (int j = 0; j < 4; j++) {
                g_h[r*64 + tx*4 + j] = acc[i][j];
                g_hbf[r*64 + tx*4 + j] = __float2bfloat16(acc[i][j]);
            }
        }
    }
}

// ---------------- CH = h @ [Wc^T | Wn^T], 512 threads (R12-proven) ----------------
__global__ __launch_bounds__(512, 2) void k_pre_mma(const uint32_t* __restrict__ BfP) {
    __shared__ __align__(16) unsigned char s_u[34816];
    __nv_bfloat16 (*s_A)[72] = (__nv_bfloat16(*)[72])s_u;
    uint32_t* s_Bf = (uint32_t*)(s_u + 18432);
    __nv_bfloat16 (*s_D)[136] = (__nv_bfloat16(*)[136])s_u;

    int r0 = blockIdx.x * 128;
    int cy = blockIdx.y;
    int tid = threadIdx.x;
    int nvalid = NATOM - r0; if (nvalid > 128) nvalid = 128;

    for (int i = tid; i < 4608; i += 512) ((uint32_t*)s_u)[i] = 0;
    __syncthreads();
    for (int i = tid; i < nvalid*32; i += 512) {
        int row = i >> 5, kk = i & 31;
        ((uint32_t*)s_u)[row*36 + kk] = ((const uint32_t*)g_hbf)[(size_t)(r0+row)*32 + kk];
    }
    for (int i = tid; i < 4096; i += 512) s_Bf[i] = BfP[cy*4096 + i];
    __syncthreads();

    int wid = tid >> 5, lane = tid & 31, gid = lane >> 2, tig = lane & 3;
    int wm = wid & 3, wn = wid >> 2;
    float acc[2][4][4];
    #pragma unroll
    for (int mt = 0; mt < 2; mt++)
        #pragma unroll
        for (int t = 0; t < 4; t++)
            #pragma unroll
            for (int j = 0; j < 4; j++) acc[mt][t][j] = 0.f;

    #pragma unroll
    for (int s = 0; s < 4; s++) {
        uint32_t a[2][4];
        #pragma unroll
        for (int mt = 0; mt < 2; mt++) {
            int row = wm*32 + mt*16 + gid;
            int kb = s*16 + 2*tig;
            a[mt][0] = *(const uint32_t*)&s_A[row][kb];
            a[mt][1] = *(const uint32_t*)&s_A[row+8][kb];
            a[mt][2] = *(const uint32_t*)&s_A[row][kb+8];
            a[mt][3] = *(const uint32_t*)&s_A[row+8][kb+8];
        }
        #pragma unroll
        for (int t = 0; t < 4; t++) {
            int gt = wn*4 + t;
            uint32_t b0 = s_Bf[((s*16+gt)*32+lane)*2];
            uint32_t b1 = s_Bf[((s*16+gt)*32+lane)*2 + 1];
            mma16816(acc[0][t], a[0], b0, b1);
            mma16816(acc[1][t], a[1], b0, b1);
        }
    }
    __syncthreads();
    #pragma unroll
    for (int mt = 0; mt < 2; mt++)
        #pragma unroll
        for (int t = 0; t < 4; t++) {
            int row = wm*32 + mt*16 + gid;
            int col = wn*32 + t*8 + 2*tig;
            *(uint32_t*)&s_D[row][col]   = packbf(acc[mt][t][0], acc[mt][t][1]);
            *(uint32_t*)&s_D[row+8][col] = packbf(acc[mt][t][2], acc[mt][t][3]);
        }
    __syncthreads();

    int ty = tid >> 4, tx = tid & 15;
    #pragma unroll
    for (int i = 0; i < 4; i++) {
        int r = ty*4 + i;
        if (r0 + r < NATOM)
            *(uint4*)&g_CHb[(size_t)(r0+r)*256 + cy*128 + tx*8] = *(const uint4*)&s_D[r][tx*8];
    }
}

// ---------------- main conv (R12-proven, untouched) ----------------
__global__ __launch_bounds__(256, 2) void k_conv_mma(const float* __restrict__ nbr_fea,
                                                     const int*   __restrict__ nbr_idx,
                                                     const float* __restrict__ bias,
                                                     const uint32_t* __restrict__ BfC,
                                                     float* __restrict__ stats1) {
    __shared__ __align__(16) unsigned char s_u[34816];
    __nv_bfloat16 (*s_A)[56] = (__nv_bfloat16(*)[56])s_u;
    uint32_t* s_Bf = (uint32_t*)(s_u + 14336);
    __nv_bfloat16 (*s_D)[136] = (__nv_bfloat16(*)[136])s_u;
    __shared__ __align__(16) __nv_bfloat16 s_cc[12][128];
    __shared__ int   s_n[128], s_nbr[128];
    __shared__ float s_sum[128], s_sq[128], s_bias[128];

    int r0 = blockIdx.x * 128;
    int a0 = r0 / 12;
    int tid = threadIdx.x;
    int nvalid = NM - r0; if (nvalid > 128) nvalid = 128;

    for (int i = tid; i < 3584; i += 256) ((uint32_t*)s_u)[i] = 0;
    __syncthreads();
    {
        const float4* src = (const float4*)(nbr_fea + (size_t)r0*41);
        int nvec = nvalid*41/4;
        for (int i = tid; i < nvec; i += 256) {
            float4 v = src[i];
            int b = i*4;
            s_A[b/41][b%41]         = __float2bfloat16(v.x);
            s_A[(b+1)/41][(b+1)%41] = __float2bfloat16(v.y);
            s_A[(b+2)/41][(b+2)%41] = __float2bfloat16(v.z);
            s_A[(b+3)/41][(b+3)%41] = __float2bfloat16(v.w);
        }
    }
    for (int i = tid; i < 3072; i += 256) s_Bf[i] = BfC[i];
    for (int i = tid; i < 12*16; i += 256) {
        int row = i >> 4, c = i & 15;
        int atom = a0 + row; if (atom > NATOM-1) atom = NATOM-1;
        *(uint4*)&s_cc[row][c*8] = *(const uint4*)&g_CHb[(size_t)atom*256 + c*8];
    }
    if (tid < 128) {
        int e = r0 + tid;
        s_nbr[tid] = (e < NM) ? nbr_idx[e] : 0;
        s_n[tid]   = (e < NM) ? e / 12 - a0 : 0;
        s_sum[tid] = 0.f; s_sq[tid] = 0.f; s_bias[tid] = bias[tid];
    }
    __syncthreads();

    int wid = tid >> 5, lane = tid & 31, gid = lane >> 2, tig = lane & 3;
    int wm = wid & 3, wn = wid >> 2;
    float acc[2][8][4];
    #pragma unroll
    for (int mt = 0; mt < 2; mt++)
        #pragma unroll
        for (int t = 0; t < 8; t++)
            #pragma unroll
            for (int j = 0; j < 4; j++) acc[mt][t][j] = 0.f;

    #pragma unroll
    for (int s = 0; s < 3; s++) {
        uint32_t a[2][4];
        #pragma unroll
        for (int mt = 0; mt < 2; mt++) {
            int row = wm*32 + mt*16 + gid;
            int kb = s*16 + 2*tig;
            a[mt][0] = *(const uint32_t*)&s_A[row][kb];
            a[mt][1] = *(const uint32_t*)&s_A[row+8][kb];
            a[mt][2] = *(const uint32_t*)&s_A[row][kb+8];
            a[mt][3] = *(const uint32_t*)&s_A[row+8][kb+8];
        }
        #pragma unroll
        for (int t = 0; t < 8; t++) {
            int gt = wn*8 + t;
            uint32_t b0 = s_Bf[((s*16+gt)*32+lane)*2];
            uint32_t b1 = s_Bf[((s*16+gt)*32+lane)*2 + 1];
            mma16816(acc[0][t], a[0], b0, b1);
            mma16816(acc[1][t], a[1], b0, b1);
        }
    }
    __syncthreads();
    #pragma unroll
    for (int mt = 0; mt < 2; mt++)
        #pragma unroll
        for (int t = 0; t < 8; t++) {
            int row = wm*32 + mt*16 + gid;
            int col = wn*64 + t*8 + 2*tig;
            *(uint32_t*)&s_D[row][col]   = packbf(acc[mt][t][0], acc[mt][t][1]);
            *(uint32_t*)&s_D[row+8][col] = packbf(acc[mt][t][2], acc[mt][t][3]);
        }
    __syncthreads();

    int ty = tid >> 4, tx = tid & 15;
    float bs[8], cs[8], cq[8];
    #pragma unroll
    for (int j = 0; j < 8; j++) { bs[j] = s_bias[tx*8 + j]; cs[j] = 0.f; cq[j] = 0.f; }

    uint4 cn4[8];
    #pragma unroll
    for (int i = 0; i < 8; i++) {
        int lr = ty*8 + i;
        cn4[i] = *(const uint4*)&g_CHb[(size_t)s_nbr[lr]*256 + 128 + tx*8];
    }
    #pragma unroll
    for (int i = 0; i < 8; i++) {
        int lr = ty*8 + i;
        int e = r0 + lr;
        if (e < NM) {
            uint4 cc4 = *(const uint4*)&s_cc[s_n[lr]][tx*8];
            const uint32_t* ccw = (const uint32_t*)&cc4;
            const uint32_t* cnw = (const uint32_t*)&cn4[i];
            const __nv_bfloat162* dd = (const __nv_bfloat162*)&s_D[lr][tx*8];
            uint32_t o[4];
            #pragma unroll
            for (int jj = 0; jj < 4; jj++) {
                float2 d2 = __bfloat1622float2(dd[jj]);
                float2 c2 = __bfloat1622float2(*(const __nv_bfloat162*)&ccw[jj]);
                float2 n2 = __bfloat1622float2(*(const __nv_bfloat162*)&cnw[jj]);
                float v0 = d2.x + c2.x + n2.x + bs[2*jj];
                float v1 = d2.y + c2.y + n2.y + bs[2*jj+1];
                cs[2*jj]   += v0; cq[2*jj]   += v0*v0;
                cs[2*jj+1] += v1; cq[2*jj+1] += v1*v1;
                o[jj] = packbf(v0, v1);
            }
            *(uint4*)&g_gatedb[(size_t)e*128 + tx*8] = make_uint4(o[0], o[1], o[2], o[3]);
        }
    }
    #pragma unroll
    for (int j = 0; j < 8; j++) {
        atomicAdd(&s_sum[tx*8+j], cs[j]);
        atomicAdd(&s_sq[tx*8+j],  cq[j]);
    }
    __syncthreads();
    if (tid < 128) {
        atomicAdd(&stats1[tid],       s_sum[tid]);
        atomicAdd(&stats1[128 + tid], s_sq[tid]);
    }
}

// ---------------- BN1-apply + activation (HW tanh sigmoid) + sum over M + BN2 stats ----------------
__global__ void k_act(const float* __restrict__ g1, const float* __restrict__ b1,
                      const float* __restrict__ stats1, float* __restrict__ stats2) {
    __shared__ float s_bnp[256];
    __shared__ float s_s[64], s_q[64];
    int tid = threadIdx.x;
    int lane = tid & 31;
    int an = blockIdx.x*8 + (tid >> 5);
    if (tid < 64) { s_s[tid] = 0.f; s_q[tid] = 0.f; }
    if (tid < 128) {
        float s = stats1[tid], q = stats1[128+tid];
        float inv = 1.f / (float)NM;
        float mu = s * inv;
        float var = q * inv - mu*mu;
        float a = g1[tid] * rsqrtf(var + BN_EPS);
        s_bnp[tid] = a;
        s_bnp[128+tid] = b1[tid] - mu*a;
    }
    __syncthreads();

    float2 af = *(const float2*)&s_bnp[2*lane];
    float2 ac = *(const float2*)&s_bnp[64 + 2*lane];
    float2 cf = *(const float2*)&s_bnp[128 + 2*lane];
    float2 cc = *(const float2*)&s_bnp[192 + 2*lane];
    const __nv_bfloat162* gp = (const __nv_bfloat162*)&g_gatedb[(size_t)an*1536];
    float sx = 0.f, sy = 0.f;
    #pragma unroll
    for (int m = 0; m < 12; m++) {
        float2 f = __bfloat1622float2(gp[m*64 + lane]);
        float2 c = __bfloat1622float2(gp[m*64 + 32 + lane]);
        sx += sigmoid_tanh(af.x*f.x + cf.x) * softplus_fast(ac.x*c.x + cc.x);
        sy += sigmoid_tanh(af.y*f.y + cf.y) * softplus_fast(ac.y*c.y + cc.y);
    }
    *(float2*)&g_summed[(size_t)an*64 + 2*lane] = make_float2(sx, sy);
    atomicAdd(&s_s[2*lane],   sx);
    atomicAdd(&s_s[2*lane+1], sy);
    atomicAdd(&s_q[2*lane],   sx*sx);
    atomicAdd(&s_q[2*lane+1], sy*sy);
    __syncthreads();
    if (tid < 64) {
        atomicAdd(&stats2[tid],      s_s[tid]);
        atomicAdd(&stats2[64 + tid], s_q[tid]);
    }
}

// ---------------- residual + softplus (fast) (+ optional fused norm) ----------------
__global__ void k_update(const float* __restrict__ g2, const float* __restrict__ b2,
                         const float* __restrict__ stats2, int do_norm) {
    __shared__ float s_bnp[128];
    __shared__ float s_nrm[4];
    int tid = threadIdx.x;
    if (tid < 64) {
        float s = stats2[tid], q = stats2[64+tid];
        float inv = 1.f / (float)NATOM;
        float mu = s * inv;
        float var = q * inv - mu*mu;
        float a = g2[tid] * rsqrtf(var + BN_EPS);
        s_bnp[tid] = a;
        s_bnp[64+tid] = b2[tid] - mu*a;
    }
    if (tid < 4) s_nrm[tid] = 0.f;
    __syncthreads();
    int idx = blockIdx.x*256 + tid;
    int j = idx & 63;
    float v = g_h[idx] + s_bnp[j]*g_summed[idx] + s_bnp[64+j];
    float r = softplus_fast(v);
    g_h[idx] = r;
    g_hbf[idx] = __float2bfloat16(r);
    if (do_norm) {
        float ss = r*r;
        #pragma unroll
        for (int off = 16; off; off >>= 1) ss += __shfl_xor_sync(0xffffffffu, ss, off);
        int la = tid >> 6;
        if ((tid & 31) == 0) atomicAdd(&s_nrm[la], ss);
        __syncthreads();
        if ((tid & 63) == 0) {
            int n = idx >> 6;
            g_inv[n] = 1.f / fmaxf(sqrtf(s_nrm[la]), 1e-12f);
        }
    }
}

// ---------------- crystal pooling ----------------
__global__ void k_pool(const int* __restrict__ cai) {
    int b = blockIdx.x, j = threadIdx.x;
    float s = 0.f;
    for (int a = 0; a < NACRY; a++) {
        int idx = cai[b*NACRY + a];
        s += g_h[(size_t)idx*64 + j] * g_inv[idx];
    }
    g_pooled[b*64 + j] = s * (1.f / (float)NACRY);
}

// ---------------- final MLP ----------------
__global__ void k_mlp(const float* __restrict__ fc1_W, const float* __restrict__ fc1_b,
                      const float* __restrict__ fc2_W, const float* __restrict__ fc2_b,
                      const float* __restrict__ out_W, const float* __restrict__ out_b,
                      float* __restrict__ props) {
    __shared__ float s_W[64*64];
    __shared__ float s_v[64];
    __shared__ float s_red[64];
    int b = blockIdx.x, j = threadIdx.x;

    s_v[j] = g_pooled[b*64 + j];
    for (int i = j; i < 4096; i += 64) s_W[i] = fc1_W[i];
    __syncthreads();
    float acc = fc1_b[j];
    for (int k = 0; k < 64; k++) acc += s_v[k] * s_W[j*64 + k];
    float z1 = softplus_f(acc);
    __syncthreads();
    s_v[j] = z1;
    for (int i = j; i < 4096; i += 64) s_W[i] = fc2_W[i];
    __syncthreads();
    acc = fc2_b[j];
    for (int k = 0; k < 64; k++) acc += s_v[k] * s_W[j*64 + k];
    float z2 = softplus_f(acc);
    s_red[j] = z2 * out_W[j];
    __syncthreads();
    for (int s = 32; s > 0; s >>= 1) {
        if (j < s) s_red[j] += s_red[j + s];
        __syncthreads();
    }
    if (j == 0) props[b] = s_red[0] + out_b[0];
}

// ---------------- launch ----------------
extern "C" void kernel_launch(void* const* d_in, const int* in_sizes, int n_in,
                              void* d_out, int out_size) {
    const float* atom_fea = (const float*)d_in[0];
    const float* nbr_fea  = (const float*)d_in[1];
    const int*   nbr_idx  = (const int*)d_in[2];
    const int*   cai      = (const int*)d_in[3];
    const float* mask     = (const float*)d_in[4];
    const float* emb_W    = (const float*)d_in[5];
    const float* conv_W   = (const float*)d_in[6];
    const float* conv_b   = (const float*)d_in[7];
    const float* bn1_g    = (const float*)d_in[8];
    const float* bn1_b    = (const float*)d_in[9];
    const float* bn2_g    = (const float*)d_in[10];
    const float* bn2_b    = (const float*)d_in[11];
    const float* fc1_W    = (const float*)d_in[12];
    const float* fc1_b    = (const float*)d_in[13];
    const float* fc2_W    = (const float*)d_in[14];
    const float* fc2_b    = (const float*)d_in[15];
    const float* out_W    = (const float*)d_in[16];
    const float* out_b    = (const float*)d_in[17];
    float* out = (float*)d_out;

    float* st1; cudaGetSymbolAddress((void**)&st1, g_stats1);
    float* st2; cudaGetSymbolAddress((void**)&st2, g_stats2);
    uint32_t* bfc; cudaGetSymbolAddress((void**)&bfc, g_BfC);
    uint32_t* bfp; cudaGetSymbolAddress((void**)&bfp, g_BfP);

    k_prepw_all<<<(NCONV*(3072+8192) + 255)/256, 256>>>(conv_W);
    k_embed<<<(NATOM + 63)/64, 256>>>(atom_fea, mask, emb_W, out + BCRY);

    for (int l = 0; l < NCONV; l++) {
        k_pre_mma<<<dim3((NATOM + 127)/128, 2), 512>>>(bfp + l*8192);
        k_conv_mma<<<(NM + 127)/128, 256>>>(nbr_fea, nbr_idx, conv_b + l*128, bfc + l*3072, st1 + l*256);
        k_act<<<NATOM/8, 256>>>(bn1_g + l*128, bn1_b + l*128, st1 + l*256, st2 + l*128);
        k_update<<<NATOM*64/256, 256>>>(bn2_g + l*64, bn2_b + l*64, st2 + l*128, (l == NCONV-1) ? 1 : 0);
    }

    k_pool<<<BCRY, 64>>>(cai);
    k_mlp<<<BCRY, 64>>>(fc1_W, fc1_b, fc2_W, fc2_b, out_W, out_b, out);
}